// round 1
// baseline (speedup 1.0000x reference)
#include <cuda_runtime.h>
#include <math.h>

#define NN 50000
#define EE 800000
#define HIDN 128
#define GG 64
#define TROW 132   // T row: 128 (T[h][c]) + 4 (B[h])

// ---------------- scratch (static device globals; no runtime allocation) ----------------
__device__ float d_q[NN * HIDN];
__device__ float d_k[NN * HIDN];
__device__ float d_v[NN * HIDN];
__device__ float d_T[NN * TROW];
__device__ float d_tmp[NN * HIDN];
__device__ float d_agg[NN * HIDN];
__device__ float d_eaP[EE * 32];
__device__ int   d_deg[NN];
__device__ int   d_cnt2[NN];
__device__ int   d_off[NN + 1];
__device__ int   d_srcPerm[EE];
__device__ int   d_posOf[EE];
__device__ float d_gsum[GG * HIDN];
__device__ unsigned d_gmaxk[GG * HIDN];
__device__ int   d_gcnt[GG];

static __device__ __forceinline__ float4 ld4(const float* p) { return *reinterpret_cast<const float4*>(p); }
static __device__ __forceinline__ void st4(float* p, float4 v) { *reinterpret_cast<float4*>(p) = v; }

static __device__ __forceinline__ unsigned enc_f(float f) {
    unsigned b = __float_as_uint(f);
    return (b & 0x80000000u) ? ~b : (b | 0x80000000u);
}
static __device__ __forceinline__ float dec_f(unsigned k) {
    return (k & 0x80000000u) ? __uint_as_float(k ^ 0x80000000u) : __uint_as_float(~k);
}

// ---------------- CSR build ----------------
__global__ void zero_csr_kernel(int n) {
    int i = blockIdx.x * blockDim.x + threadIdx.x;
    if (i < n) { d_deg[i] = 0; d_cnt2[i] = 0; }
}

__global__ void hist_kernel(const int* __restrict__ dst, int E) {
    int e = blockIdx.x * blockDim.x + threadIdx.x;
    if (e < E) atomicAdd(&d_deg[dst[e]], 1);
}

// single-block scan over d_deg -> exclusive offsets d_off
__global__ void scan_kernel(int n) {
    __shared__ int s[32];
    int tid = threadIdx.x, lane = tid & 31, wid = tid >> 5;
    int base = 0;
    if (tid == 0) d_off[0] = 0;
    for (int start = 0; start < n; start += 1024) {
        int i = start + tid;
        int v = (i < n) ? d_deg[i] : 0;
#pragma unroll
        for (int o = 1; o < 32; o <<= 1) {
            int t = __shfl_up_sync(0xffffffffu, v, o);
            if (lane >= o) v += t;
        }
        if (lane == 31) s[wid] = v;
        __syncthreads();
        if (wid == 0) {
            int w = s[lane];
#pragma unroll
            for (int o = 1; o < 32; o <<= 1) {
                int t = __shfl_up_sync(0xffffffffu, w, o);
                if (lane >= o) w += t;
            }
            s[lane] = w;
        }
        __syncthreads();
        int add = base + (wid ? s[wid - 1] : 0);
        v += add;
        if (i < n) d_off[i + 1] = v;
        base += s[31];
        __syncthreads();
    }
}

__global__ void scatter_kernel(const int* __restrict__ src, const int* __restrict__ dst, int E) {
    int e = blockIdx.x * blockDim.x + threadIdx.x;
    if (e >= E) return;
    int d = dst[e];
    int p = d_off[d] + atomicAdd(&d_cnt2[d], 1);
    d_srcPerm[p] = src[e];
    d_posOf[e] = p;
}

// edge projection: eaP[pos[e]] = edge_attr[e] @ W_ep + b_ep   (one warp per edge)
__global__ void ea_proj_kernel(const float* __restrict__ eattr,
                               const float* __restrict__ W_ep,
                               const float* __restrict__ b_ep, int E) {
    __shared__ float Ws[32][33];
    __shared__ float bs[32];
    int tid = threadIdx.x;
    for (int i = tid; i < 1024; i += blockDim.x) Ws[i >> 5][i & 31] = W_ep[i];
    if (tid < 32) bs[tid] = b_ep[tid];
    __syncthreads();
    int gw = (blockIdx.x * blockDim.x + tid) >> 5;
    int lane = tid & 31;
    if (gw >= E) return;
    float a = eattr[gw * 32 + lane];
    float acc = bs[lane];
#pragma unroll
    for (int c = 0; c < 32; c++)
        acc = fmaf(__shfl_sync(0xffffffffu, a, c), Ws[c][lane], acc);
    d_eaP[(size_t)d_posOf[gw] * 32 + lane] = acc;
}

// ---------------- GEMM: C[M,128] = A[M,128] @ W[128,128] + bias ----------------
__global__ void __launch_bounds__(256) gemm128_kernel(const float* __restrict__ A,
                                                      const float* __restrict__ W,
                                                      const float* __restrict__ bias,
                                                      float* __restrict__ C, int M) {
    __shared__ float As[32][132];   // transposed: As[k][row]
    __shared__ float Bs[32][128];   // Bs[k][col]
    int tid = threadIdx.x;
    int tx = tid & 15, ty = tid >> 4;
    int rowbase = blockIdx.x * 128;
    int r0 = ty * 4, r1 = 64 + ty * 4;
    int c0 = tx * 4, c1 = 64 + tx * 4;

    float acc[8][8];
#pragma unroll
    for (int i = 0; i < 8; i++)
#pragma unroll
        for (int j = 0; j < 8; j++) acc[i][j] = 0.f;

    for (int kc = 0; kc < 128; kc += 32) {
#pragma unroll
        for (int i = 0; i < 4; i++) {
            int f = tid + i * 256;       // 0..1023 float4s
            int row = f >> 3;            // 0..127
            int kq = f & 7;
            float4 a = (rowbase + row < M) ? ld4(A + (size_t)(rowbase + row) * 128 + kc + kq * 4)
                                           : make_float4(0.f, 0.f, 0.f, 0.f);
            As[kq * 4 + 0][row] = a.x;
            As[kq * 4 + 1][row] = a.y;
            As[kq * 4 + 2][row] = a.z;
            As[kq * 4 + 3][row] = a.w;
        }
#pragma unroll
        for (int i = 0; i < 4; i++) {
            int f = tid + i * 256;
            int k = f >> 5;
            int cq = f & 31;
            *reinterpret_cast<float4*>(&Bs[k][cq * 4]) = ld4(W + (size_t)(kc + k) * 128 + cq * 4);
        }
        __syncthreads();
#pragma unroll
        for (int k = 0; k < 32; k++) {
            float4 a0 = *reinterpret_cast<float4*>(&As[k][r0]);
            float4 a1 = *reinterpret_cast<float4*>(&As[k][r1]);
            float4 b0 = *reinterpret_cast<float4*>(&Bs[k][c0]);
            float4 b1 = *reinterpret_cast<float4*>(&Bs[k][c1]);
            float av[8] = {a0.x, a0.y, a0.z, a0.w, a1.x, a1.y, a1.z, a1.w};
            float bv[8] = {b0.x, b0.y, b0.z, b0.w, b1.x, b1.y, b1.z, b1.w};
#pragma unroll
            for (int i = 0; i < 8; i++)
#pragma unroll
                for (int j = 0; j < 8; j++) acc[i][j] = fmaf(av[i], bv[j], acc[i][j]);
        }
        __syncthreads();
    }

    float4 bb0 = ld4(bias + c0), bb1 = ld4(bias + c1);
#pragma unroll
    for (int i = 0; i < 8; i++) {
        int row = rowbase + ((i < 4) ? (r0 + i) : (r1 + i - 4));
        if (row < M) {
            float4 o0 = make_float4(acc[i][0] + bb0.x, acc[i][1] + bb0.y, acc[i][2] + bb0.z, acc[i][3] + bb0.w);
            float4 o1 = make_float4(acc[i][4] + bb1.x, acc[i][5] + bb1.y, acc[i][6] + bb1.z, acc[i][7] + bb1.w);
            st4(C + (size_t)row * 128 + c0, o0);
            st4(C + (size_t)row * 128 + c1, o1);
        }
    }
}

// ---------------- T[n][h][c] = sum_d q[n,h*32+d] * We[c][h*32+d];  B[n][h] = sum_d q*be ----------------
__global__ void t_kernel(const float* __restrict__ q,
                         const float* __restrict__ We_l,
                         const float* __restrict__ be_l, int n) {
    __shared__ float WeT[128][36];  // WeT[j][c]
    int tid = threadIdx.x;
    for (int i = tid; i < 32 * 128; i += blockDim.x) {
        int c = i >> 7, j = i & 127;
        WeT[j][c] = We_l[i];
    }
    __syncthreads();
    int gw = (blockIdx.x * blockDim.x + tid) >> 5;
    int lane = tid & 31;
    if (gw >= n) return;
    int h = lane >> 3, cl = lane & 7;
    float4 qv = ld4(q + (size_t)gw * 128 + lane * 4);
    // bias-fold term B[h] = q[h,:] . be[h,:]
    float4 be4 = ld4(be_l + lane * 4);
    float bp = qv.x * be4.x + qv.y * be4.y + qv.z * be4.z + qv.w * be4.w;
    bp += __shfl_xor_sync(0xffffffffu, bp, 1);
    bp += __shfl_xor_sync(0xffffffffu, bp, 2);
    bp += __shfl_xor_sync(0xffffffffu, bp, 4);
    if (cl == 0) d_T[(size_t)gw * TROW + 128 + h] = bp;

    float4 acc = make_float4(0.f, 0.f, 0.f, 0.f);
#pragma unroll
    for (int d4 = 0; d4 < 8; d4++) {
        int sl = h * 8 + d4;
        float q0 = __shfl_sync(0xffffffffu, qv.x, sl);
        float q1 = __shfl_sync(0xffffffffu, qv.y, sl);
        float q2 = __shfl_sync(0xffffffffu, qv.z, sl);
        float q3 = __shfl_sync(0xffffffffu, qv.w, sl);
        int jb = h * 32 + d4 * 4;
        float4 w0 = *reinterpret_cast<float4*>(&WeT[jb + 0][cl * 4]);
        float4 w1 = *reinterpret_cast<float4*>(&WeT[jb + 1][cl * 4]);
        float4 w2 = *reinterpret_cast<float4*>(&WeT[jb + 2][cl * 4]);
        float4 w3 = *reinterpret_cast<float4*>(&WeT[jb + 3][cl * 4]);
        acc.x = fmaf(q0, w0.x, acc.x); acc.y = fmaf(q0, w0.y, acc.y); acc.z = fmaf(q0, w0.z, acc.z); acc.w = fmaf(q0, w0.w, acc.w);
        acc.x = fmaf(q1, w1.x, acc.x); acc.y = fmaf(q1, w1.y, acc.y); acc.z = fmaf(q1, w1.z, acc.z); acc.w = fmaf(q1, w1.w, acc.w);
        acc.x = fmaf(q2, w2.x, acc.x); acc.y = fmaf(q2, w2.y, acc.y); acc.z = fmaf(q2, w2.z, acc.z); acc.w = fmaf(q2, w2.w, acc.w);
        acc.x = fmaf(q3, w3.x, acc.x); acc.y = fmaf(q3, w3.y, acc.y); acc.z = fmaf(q3, w3.z, acc.z); acc.w = fmaf(q3, w3.w, acc.w);
    }
    st4(&d_T[(size_t)gw * TROW + h * 32 + cl * 4], acc);
}

// ---------------- edge attention + aggregation: one warp per destination node ----------------
__global__ void edge_agg_kernel(int n) {
    int gw = (blockIdx.x * blockDim.x + threadIdx.x) >> 5;
    int lane = threadIdx.x & 31;
    if (gw >= n) return;
    int h = lane >> 3, cl = lane & 7;
    const float scale = 0.17677669529663687f;  // 1/sqrt(32)

    float4 qv = ld4(d_q + (size_t)gw * 128 + lane * 4);
    float4 Tv = ld4(d_T + (size_t)gw * TROW + h * 32 + cl * 4);
    float  Bh = d_T[(size_t)gw * TROW + 128 + h];
    float4 acc = make_float4(0.f, 0.f, 0.f, 0.f);

    int jb = d_off[gw], je = d_off[gw + 1];
    for (int j = jb; j < je; j++) {
        int s = d_srcPerm[j];
        float4 kv = ld4(d_k + (size_t)s * 128 + lane * 4);
        float4 ev = ld4(d_eaP + (size_t)j * 32 + cl * 4);
        float p = qv.x * kv.x + qv.y * kv.y + qv.z * kv.z + qv.w * kv.w
                + ev.x * Tv.x + ev.y * Tv.y + ev.z * Tv.z + ev.w * Tv.w;
        p += __shfl_xor_sync(0xffffffffu, p, 1);
        p += __shfl_xor_sync(0xffffffffu, p, 2);
        p += __shfl_xor_sync(0xffffffffu, p, 4);
        float amy = (p + Bh) * scale;
        float a0 = __shfl_sync(0xffffffffu, amy, 0);
        float a1 = __shfl_sync(0xffffffffu, amy, 8);
        float a2 = __shfl_sync(0xffffffffu, amy, 16);
        float a3 = __shfl_sync(0xffffffffu, amy, 24);
        float m = fmaxf(fmaxf(a0, a1), fmaxf(a2, a3));
        float e0 = __expf(a0 - m), e1 = __expf(a1 - m), e2 = __expf(a2 - m), e3 = __expf(a3 - m);
        float w = __expf(amy - m) / (e0 + e1 + e2 + e3);
        float4 vv = ld4(d_v + (size_t)s * 128 + lane * 4);
        acc.x = fmaf(w, vv.x, acc.x);
        acc.y = fmaf(w, vv.y, acc.y);
        acc.z = fmaf(w, vv.z, acc.z);
        acc.w = fmaf(w, vv.w, acc.w);
    }
    st4(d_agg + (size_t)gw * 128 + lane * 4, acc);
}

// ---------------- h = LayerNorm(tmp + h) * g + b   (one warp per node) ----------------
__global__ void ln_kernel(float* __restrict__ h,
                          const float* __restrict__ g,
                          const float* __restrict__ b, int n) {
    int gw = (blockIdx.x * blockDim.x + threadIdx.x) >> 5;
    int lane = threadIdx.x & 31;
    if (gw >= n) return;
    float4 t = ld4(d_tmp + (size_t)gw * 128 + lane * 4);
    float4 hv = ld4(h + (size_t)gw * 128 + lane * 4);
    float4 s = make_float4(t.x + hv.x, t.y + hv.y, t.z + hv.z, t.w + hv.w);
    float sum = s.x + s.y + s.z + s.w;
#pragma unroll
    for (int o = 16; o >= 1; o >>= 1) sum += __shfl_xor_sync(0xffffffffu, sum, o);
    float mu = sum * (1.f / 128.f);
    float dx = s.x - mu, dy = s.y - mu, dz = s.z - mu, dw = s.w - mu;
    float sq = dx * dx + dy * dy + dz * dz + dw * dw;
#pragma unroll
    for (int o = 16; o >= 1; o >>= 1) sq += __shfl_xor_sync(0xffffffffu, sq, o);
    float inv = rsqrtf(sq * (1.f / 128.f) + 1e-5f);
    float4 gg = ld4(g + lane * 4), bb = ld4(b + lane * 4);
    float4 o4 = make_float4(dx * inv * gg.x + bb.x, dy * inv * gg.y + bb.y,
                            dz * inv * gg.z + bb.z, dw * inv * gg.w + bb.w);
    st4(h + (size_t)gw * 128 + lane * 4, o4);
}

// ---------------- pooling ----------------
__global__ void pool_init_kernel() {
    int i = blockIdx.x * blockDim.x + threadIdx.x;
    if (i < GG * HIDN) { d_gsum[i] = 0.f; d_gmaxk[i] = 0u; }
    if (i < GG) d_gcnt[i] = 0;
}

#define NPB 256
__global__ void pool_kernel(const float* __restrict__ h, const int* __restrict__ batch, int n) {
    int c = threadIdx.x;  // 0..127
    int b0 = blockIdx.x * NPB;
    if (b0 >= n) return;
    int b1 = min(b0 + NPB, n);
    int g = batch[b0];
    float asum = 0.f, amax = -3.402823466e38f;
    int cnt = 0;
    for (int i = b0; i < b1; i++) {
        int gn = batch[i];
        if (gn != g) {
            atomicAdd(&d_gsum[g * HIDN + c], asum);
            atomicMax(&d_gmaxk[g * HIDN + c], enc_f(amax));
            if (c == 0) atomicAdd(&d_gcnt[g], cnt);
            g = gn; asum = 0.f; amax = -3.402823466e38f; cnt = 0;
        }
        float val = h[(size_t)i * HIDN + c];
        asum += val;
        amax = fmaxf(amax, val);
        cnt++;
    }
    atomicAdd(&d_gsum[g * HIDN + c], asum);
    atomicMax(&d_gmaxk[g * HIDN + c], enc_f(amax));
    if (c == 0) atomicAdd(&d_gcnt[g], cnt);
}

// ---------------- graph head: relu([mean|max|sum] @ W1 + b1) @ W2 + b2 ----------------
__global__ void mlp_kernel(const float* __restrict__ W1, const float* __restrict__ b1,
                           const float* __restrict__ W2, const float* __restrict__ b2,
                           float* __restrict__ gout) {
    __shared__ float pooled[384];
    __shared__ float t[128];
    int g = blockIdx.x, c = threadIdx.x;
    float cnt = fmaxf((float)d_gcnt[g], 1.f);
    float sv = d_gsum[g * HIDN + c];
    pooled[c] = sv / cnt;
    pooled[128 + c] = dec_f(d_gmaxk[g * HIDN + c]);
    pooled[256 + c] = sv;
    __syncthreads();
    float acc = b1[c];
#pragma unroll 8
    for (int kk = 0; kk < 384; kk++) acc = fmaf(pooled[kk], W1[kk * 128 + c], acc);
    t[c] = fmaxf(acc, 0.f);
    __syncthreads();
    float o = b2[c];
#pragma unroll 8
    for (int kk = 0; kk < 128; kk++) o = fmaf(t[kk], W2[kk * 128 + c], o);
    gout[g * 128 + c] = o;
}

// ---------------- driver ----------------
extern "C" void kernel_launch(void* const* d_in, const int* in_sizes, int n_in,
                              void* d_out, int out_size) {
    const float* x     = (const float*)d_in[0];
    const int*   ei    = (const int*)d_in[1];
    const float* eattr = (const float*)d_in[2];
    const int*   batch = (const int*)d_in[3];
    const float* W_in  = (const float*)d_in[4];
    const float* b_in  = (const float*)d_in[5];
    const float* Wq    = (const float*)d_in[6];
    const float* bq    = (const float*)d_in[7];
    const float* Wk    = (const float*)d_in[8];
    const float* bk    = (const float*)d_in[9];
    const float* Wv    = (const float*)d_in[10];
    const float* bv    = (const float*)d_in[11];
    const float* We    = (const float*)d_in[12];
    const float* be    = (const float*)d_in[13];
    const float* Wo    = (const float*)d_in[14];
    const float* bo    = (const float*)d_in[15];
    const float* ln_g  = (const float*)d_in[16];
    const float* ln_b  = (const float*)d_in[17];
    const float* W_ep  = (const float*)d_in[18];
    const float* b_ep  = (const float*)d_in[19];
    const float* W1    = (const float*)d_in[20];
    const float* b1    = (const float*)d_in[21];
    const float* W2    = (const float*)d_in[22];
    const float* b2    = (const float*)d_in[23];

    int N = in_sizes[0] / 128;
    int E = in_sizes[1] / 2;

    float* out  = (float*)d_out;
    float* h    = out;                       // [N,128] lives directly in d_out
    float* gout = out + (size_t)N * HIDN;    // [G,128]

    void *pq, *pk, *pv, *ptmp, *pagg;
    cudaGetSymbolAddress(&pq, d_q);
    cudaGetSymbolAddress(&pk, d_k);
    cudaGetSymbolAddress(&pv, d_v);
    cudaGetSymbolAddress(&ptmp, d_tmp);
    cudaGetSymbolAddress(&pagg, d_agg);

    const int* src = ei;
    const int* dst = ei + E;

    int gE = (E + 255) / 256;
    int gN = (N + 255) / 256;
    int gW = (N + 7) / 8;         // warp-per-node kernels, 256-thread blocks
    int gEW = (E + 7) / 8;        // warp-per-edge
    int gGemm = (N + 127) / 128;

    // CSR build + edge projection (layer-independent)
    zero_csr_kernel<<<gN, 256>>>(N);
    hist_kernel<<<gE, 256>>>(dst, E);
    scan_kernel<<<1, 1024>>>(N);
    scatter_kernel<<<gE, 256>>>(src, dst, E);
    ea_proj_kernel<<<gEW, 256>>>(eattr, W_ep, b_ep, E);

    // input projection: h = x @ W_in + b_in
    gemm128_kernel<<<gGemm, 256>>>(x, W_in, b_in, h, N);

    for (int l = 0; l < 3; l++) {
        const float* Wq_l = Wq + (size_t)l * 128 * 128;
        const float* Wk_l = Wk + (size_t)l * 128 * 128;
        const float* Wv_l = Wv + (size_t)l * 128 * 128;
        const float* Wo_l = Wo + (size_t)l * 128 * 128;
        const float* We_l = We + (size_t)l * 32 * 128;

        gemm128_kernel<<<gGemm, 256>>>(h, Wq_l, bq + l * 128, (float*)pq, N);
        gemm128_kernel<<<gGemm, 256>>>(h, Wk_l, bk + l * 128, (float*)pk, N);
        gemm128_kernel<<<gGemm, 256>>>(h, Wv_l, bv + l * 128, (float*)pv, N);
        t_kernel<<<gW, 256>>>((const float*)pq, We_l, be + l * 128, N);
        edge_agg_kernel<<<gW, 256>>>(N);
        gemm128_kernel<<<gGemm, 256>>>((const float*)pagg, Wo_l, bo + l * 128, (float*)ptmp, N);
        ln_kernel<<<gW, 256>>>(h, ln_g + l * 128, ln_b + l * 128, N);
    }

    pool_init_kernel<<<(GG * HIDN + 255) / 256, 256>>>();
    pool_kernel<<<(N + NPB - 1) / NPB, 128>>>(h, batch, N);
    mlp_kernel<<<GG, 128>>>(W1, b1, W2, b2, gout);
}

// round 9
// speedup vs baseline: 1.0440x; 1.0440x over previous
#include <cuda_runtime.h>
#include <math.h>

#define NN 50000
#define EE 800000
#define HIDN 128
#define GG 64
#define TROW 132   // T row: 128 (T[h][c]) + 4 (B[h])

// ---------------- scratch (static device globals; no runtime allocation) ----------------
__device__ float d_q[NN * HIDN];
__device__ float d_k[NN * HIDN];
__device__ float d_v[NN * HIDN];
__device__ float d_T[NN * TROW];
__device__ float d_tmp[NN * HIDN];
__device__ float d_agg[NN * HIDN];
__device__ float d_eaP[EE * 32];
__device__ int   d_deg[NN];
__device__ int   d_cnt2[NN];
__device__ int   d_off[NN + 1];
__device__ int   d_srcPerm[EE];
__device__ int   d_posOf[EE];
__device__ float d_gsum[GG * HIDN];
__device__ unsigned d_gmaxk[GG * HIDN];
__device__ int   d_gcnt[GG];

static __device__ __forceinline__ float4 ld4(const float* p) { return *reinterpret_cast<const float4*>(p); }
static __device__ __forceinline__ void st4(float* p, float4 v) { *reinterpret_cast<float4*>(p) = v; }

static __device__ __forceinline__ unsigned enc_f(float f) {
    unsigned b = __float_as_uint(f);
    return (b & 0x80000000u) ? ~b : (b | 0x80000000u);
}
static __device__ __forceinline__ float dec_f(unsigned k) {
    return (k & 0x80000000u) ? __uint_as_float(k ^ 0x80000000u) : __uint_as_float(~k);
}

// ---------------- CSR build ----------------
__global__ void zero_csr_kernel(int n) {
    int i = blockIdx.x * blockDim.x + threadIdx.x;
    if (i < n) { d_deg[i] = 0; d_cnt2[i] = 0; }
}

__global__ void hist_kernel(const int* __restrict__ dst, int E) {
    int e = blockIdx.x * blockDim.x + threadIdx.x;
    if (e < E) atomicAdd(&d_deg[dst[e]], 1);
}

// single-block scan over d_deg -> exclusive offsets d_off
__global__ void scan_kernel(int n) {
    __shared__ int s[32];
    int tid = threadIdx.x, lane = tid & 31, wid = tid >> 5;
    int base = 0;
    if (tid == 0) d_off[0] = 0;
    for (int start = 0; start < n; start += 1024) {
        int i = start + tid;
        int v = (i < n) ? d_deg[i] : 0;
#pragma unroll
        for (int o = 1; o < 32; o <<= 1) {
            int t = __shfl_up_sync(0xffffffffu, v, o);
            if (lane >= o) v += t;
        }
        if (lane == 31) s[wid] = v;
        __syncthreads();
        if (wid == 0) {
            int w = s[lane];
#pragma unroll
            for (int o = 1; o < 32; o <<= 1) {
                int t = __shfl_up_sync(0xffffffffu, w, o);
                if (lane >= o) w += t;
            }
            s[lane] = w;
        }
        __syncthreads();
        int add = base + (wid ? s[wid - 1] : 0);
        v += add;
        if (i < n) d_off[i + 1] = v;
        base += s[31];
        __syncthreads();
    }
}

__global__ void scatter_kernel(const int* __restrict__ src, const int* __restrict__ dst, int E) {
    int e = blockIdx.x * blockDim.x + threadIdx.x;
    if (e >= E) return;
    int d = dst[e];
    int p = d_off[d] + atomicAdd(&d_cnt2[d], 1);
    d_srcPerm[p] = src[e];
    d_posOf[e] = p;
}

// edge projection: eaP[pos[e]] = edge_attr[e] @ W_ep + b_ep   (one warp per edge)
__global__ void ea_proj_kernel(const float* __restrict__ eattr,
                               const float* __restrict__ W_ep,
                               const float* __restrict__ b_ep, int E) {
    __shared__ float Ws[32][33];
    __shared__ float bs[32];
    int tid = threadIdx.x;
    for (int i = tid; i < 1024; i += blockDim.x) Ws[i >> 5][i & 31] = W_ep[i];
    if (tid < 32) bs[tid] = b_ep[tid];
    __syncthreads();
    int gw = (blockIdx.x * blockDim.x + tid) >> 5;
    int lane = tid & 31;
    if (gw >= E) return;
    float a = eattr[gw * 32 + lane];
    float acc = bs[lane];
#pragma unroll
    for (int c = 0; c < 32; c++)
        acc = fmaf(__shfl_sync(0xffffffffu, a, c), Ws[c][lane], acc);
    d_eaP[(size_t)d_posOf[gw] * 32 + lane] = acc;
}

// ---------------- GEMM: C[M,128] = A[M,128] @ W[128,128] + bias (round-1 verbatim) ----------------
__global__ void __launch_bounds__(256) gemm128_kernel(const float* __restrict__ A,
                                                      const float* __restrict__ W,
                                                      const float* __restrict__ bias,
                                                      float* __restrict__ C, int M) {
    __shared__ float As[32][132];   // transposed: As[k][row]
    __shared__ float Bs[32][128];   // Bs[k][col]
    int tid = threadIdx.x;
    int tx = tid & 15, ty = tid >> 4;
    int rowbase = blockIdx.x * 128;
    int r0 = ty * 4, r1 = 64 + ty * 4;
    int c0 = tx * 4, c1 = 64 + tx * 4;

    float acc[8][8];
#pragma unroll
    for (int i = 0; i < 8; i++)
#pragma unroll
        for (int j = 0; j < 8; j++) acc[i][j] = 0.f;

    for (int kc = 0; kc < 128; kc += 32) {
#pragma unroll
        for (int i = 0; i < 4; i++) {
            int f = tid + i * 256;       // 0..1023 float4s
            int row = f >> 3;            // 0..127
            int kq = f & 7;
            float4 a = (rowbase + row < M) ? ld4(A + (size_t)(rowbase + row) * 128 + kc + kq * 4)
                                           : make_float4(0.f, 0.f, 0.f, 0.f);
            As[kq * 4 + 0][row] = a.x;
            As[kq * 4 + 1][row] = a.y;
            As[kq * 4 + 2][row] = a.z;
            As[kq * 4 + 3][row] = a.w;
        }
#pragma unroll
        for (int i = 0; i < 4; i++) {
            int f = tid + i * 256;
            int k = f >> 5;
            int cq = f & 31;
            *reinterpret_cast<float4*>(&Bs[k][cq * 4]) = ld4(W + (size_t)(kc + k) * 128 + cq * 4);
        }
        __syncthreads();
#pragma unroll
        for (int k = 0; k < 32; k++) {
            float4 a0 = *reinterpret_cast<float4*>(&As[k][r0]);
            float4 a1 = *reinterpret_cast<float4*>(&As[k][r1]);
            float4 b0 = *reinterpret_cast<float4*>(&Bs[k][c0]);
            float4 b1 = *reinterpret_cast<float4*>(&Bs[k][c1]);
            float av[8] = {a0.x, a0.y, a0.z, a0.w, a1.x, a1.y, a1.z, a1.w};
            float bv[8] = {b0.x, b0.y, b0.z, b0.w, b1.x, b1.y, b1.z, b1.w};
#pragma unroll
            for (int i = 0; i < 8; i++)
#pragma unroll
                for (int j = 0; j < 8; j++) acc[i][j] = fmaf(av[i], bv[j], acc[i][j]);
        }
        __syncthreads();
    }

    float4 bb0 = ld4(bias + c0), bb1 = ld4(bias + c1);
#pragma unroll
    for (int i = 0; i < 8; i++) {
        int row = rowbase + ((i < 4) ? (r0 + i) : (r1 + i - 4));
        if (row < M) {
            float4 o0 = make_float4(acc[i][0] + bb0.x, acc[i][1] + bb0.y, acc[i][2] + bb0.z, acc[i][3] + bb0.w);
            float4 o1 = make_float4(acc[i][4] + bb1.x, acc[i][5] + bb1.y, acc[i][6] + bb1.z, acc[i][7] + bb1.w);
            st4(C + (size_t)row * 128 + c0, o0);
            st4(C + (size_t)row * 128 + c1, o1);
        }
    }
}

// ---------------- T[n][h][c] = sum_d q[n,h*32+d] * We[c][h*32+d];  B[n][h] = sum_d q*be ----------------
__global__ void t_kernel(const float* __restrict__ q,
                         const float* __restrict__ We_l,
                         const float* __restrict__ be_l, int n) {
    __shared__ float WeT[128][36];  // WeT[j][c]
    int tid = threadIdx.x;
    for (int i = tid; i < 32 * 128; i += blockDim.x) {
        int c = i >> 7, j = i & 127;
        WeT[j][c] = We_l[i];
    }
    __syncthreads();
    int gw = (blockIdx.x * blockDim.x + tid) >> 5;
    int lane = tid & 31;
    if (gw >= n) return;
    int h = lane >> 3, cl = lane & 7;
    float4 qv = ld4(q + (size_t)gw * 128 + lane * 4);
    float4 be4 = ld4(be_l + lane * 4);
    float bp = qv.x * be4.x + qv.y * be4.y + qv.z * be4.z + qv.w * be4.w;
    bp += __shfl_xor_sync(0xffffffffu, bp, 1);
    bp += __shfl_xor_sync(0xffffffffu, bp, 2);
    bp += __shfl_xor_sync(0xffffffffu, bp, 4);
    if (cl == 0) d_T[(size_t)gw * TROW + 128 + h] = bp;

    float4 acc = make_float4(0.f, 0.f, 0.f, 0.f);
#pragma unroll
    for (int d4 = 0; d4 < 8; d4++) {
        int sl = h * 8 + d4;
        float q0 = __shfl_sync(0xffffffffu, qv.x, sl);
        float q1 = __shfl_sync(0xffffffffu, qv.y, sl);
        float q2 = __shfl_sync(0xffffffffu, qv.z, sl);
        float q3 = __shfl_sync(0xffffffffu, qv.w, sl);
        int jb = h * 32 + d4 * 4;
        float4 w0 = *reinterpret_cast<float4*>(&WeT[jb + 0][cl * 4]);
        float4 w1 = *reinterpret_cast<float4*>(&WeT[jb + 1][cl * 4]);
        float4 w2 = *reinterpret_cast<float4*>(&WeT[jb + 2][cl * 4]);
        float4 w3 = *reinterpret_cast<float4*>(&WeT[jb + 3][cl * 4]);
        acc.x = fmaf(q0, w0.x, acc.x); acc.y = fmaf(q0, w0.y, acc.y); acc.z = fmaf(q0, w0.z, acc.z); acc.w = fmaf(q0, w0.w, acc.w);
        acc.x = fmaf(q1, w1.x, acc.x); acc.y = fmaf(q1, w1.y, acc.y); acc.z = fmaf(q1, w1.z, acc.z); acc.w = fmaf(q1, w1.w, acc.w);
        acc.x = fmaf(q2, w2.x, acc.x); acc.y = fmaf(q2, w2.y, acc.y); acc.z = fmaf(q2, w2.z, acc.z); acc.w = fmaf(q2, w2.w, acc.w);
        acc.x = fmaf(q3, w3.x, acc.x); acc.y = fmaf(q3, w3.y, acc.y); acc.z = fmaf(q3, w3.z, acc.z); acc.w = fmaf(q3, w3.w, acc.w);
    }
    st4(&d_T[(size_t)gw * TROW + h * 32 + cl * 4], acc);
}

// ---------------- edge attention + aggregation: one warp per destination node ----------------
__global__ void edge_agg_kernel(int n) {
    int gw = (blockIdx.x * blockDim.x + threadIdx.x) >> 5;
    int lane = threadIdx.x & 31;
    if (gw >= n) return;
    int h = lane >> 3, cl = lane & 7;
    const float scale = 0.17677669529663687f;  // 1/sqrt(32)

    float4 qv = ld4(d_q + (size_t)gw * 128 + lane * 4);
    float4 Tv = ld4(d_T + (size_t)gw * TROW + h * 32 + cl * 4);
    float  Bh = d_T[(size_t)gw * TROW + 128 + h];
    float4 acc = make_float4(0.f, 0.f, 0.f, 0.f);

    int jb = d_off[gw], je = d_off[gw + 1];
    int s = (jb < je) ? d_srcPerm[jb] : 0;
    for (int j = jb; j < je; j++) {
        int s_next = (j + 1 < je) ? d_srcPerm[j + 1] : 0;   // prefetch next src idx
        float4 kv = ld4(d_k + (size_t)s * 128 + lane * 4);
        float4 ev = ld4(d_eaP + (size_t)j * 32 + cl * 4);
        float4 vv = ld4(d_v + (size_t)s * 128 + lane * 4);
        float p = qv.x * kv.x + qv.y * kv.y + qv.z * kv.z + qv.w * kv.w
                + ev.x * Tv.x + ev.y * Tv.y + ev.z * Tv.z + ev.w * Tv.w;
        p += __shfl_xor_sync(0xffffffffu, p, 1);
        p += __shfl_xor_sync(0xffffffffu, p, 2);
        p += __shfl_xor_sync(0xffffffffu, p, 4);
        float amy = (p + Bh) * scale;
        float a0 = __shfl_sync(0xffffffffu, amy, 0);
        float a1 = __shfl_sync(0xffffffffu, amy, 8);
        float a2 = __shfl_sync(0xffffffffu, amy, 16);
        float a3 = __shfl_sync(0xffffffffu, amy, 24);
        float m = fmaxf(fmaxf(a0, a1), fmaxf(a2, a3));
        float e0 = __expf(a0 - m), e1 = __expf(a1 - m), e2 = __expf(a2 - m), e3 = __expf(a3 - m);
        float w = __expf(amy - m) / (e0 + e1 + e2 + e3);
        acc.x = fmaf(w, vv.x, acc.x);
        acc.y = fmaf(w, vv.y, acc.y);
        acc.z = fmaf(w, vv.z, acc.z);
        acc.w = fmaf(w, vv.w, acc.w);
        s = s_next;
    }
    st4(d_agg + (size_t)gw * 128 + lane * 4, acc);
}

// ---------------- h = LayerNorm(tmp + h) * g + b   (one warp per node; round-1 verbatim) ----------------
__global__ void ln_kernel(float* __restrict__ h,
                          const float* __restrict__ g,
                          const float* __restrict__ b, int n) {
    int gw = (blockIdx.x * blockDim.x + threadIdx.x) >> 5;
    int lane = threadIdx.x & 31;
    if (gw >= n) return;
    float4 t = ld4(d_tmp + (size_t)gw * 128 + lane * 4);
    float4 hv = ld4(h + (size_t)gw * 128 + lane * 4);
    float4 s = make_float4(t.x + hv.x, t.y + hv.y, t.z + hv.z, t.w + hv.w);
    float sum = s.x + s.y + s.z + s.w;
#pragma unroll
    for (int o = 16; o >= 1; o >>= 1) sum += __shfl_xor_sync(0xffffffffu, sum, o);
    float mu = sum * (1.f / 128.f);
    float dx = s.x - mu, dy = s.y - mu, dz = s.z - mu, dw = s.w - mu;
    float sq = dx * dx + dy * dy + dz * dz + dw * dw;
#pragma unroll
    for (int o = 16; o >= 1; o >>= 1) sq += __shfl_xor_sync(0xffffffffu, sq, o);
    float inv = rsqrtf(sq * (1.f / 128.f) + 1e-5f);
    float4 gg = ld4(g + lane * 4), bb = ld4(b + lane * 4);
    float4 o4 = make_float4(dx * inv * gg.x + bb.x, dy * inv * gg.y + bb.y,
                            dz * inv * gg.z + bb.z, dw * inv * gg.w + bb.w);
    st4(h + (size_t)gw * 128 + lane * 4, o4);
}

// ---------------- pooling ----------------
__global__ void pool_init_kernel() {
    int i = blockIdx.x * blockDim.x + threadIdx.x;
    if (i < GG * HIDN) { d_gsum[i] = 0.f; d_gmaxk[i] = 0u; }
    if (i < GG) d_gcnt[i] = 0;
}

#define NPB 256
__global__ void pool_kernel(const float* __restrict__ h, const int* __restrict__ batch, int n) {
    int c = threadIdx.x;  // 0..127
    int b0 = blockIdx.x * NPB;
    if (b0 >= n) return;
    int b1 = min(b0 + NPB, n);
    int g = batch[b0];
    float asum = 0.f, amax = -3.402823466e38f;
    int cnt = 0;
    for (int i = b0; i < b1; i++) {
        int gn = batch[i];
        if (gn != g) {
            atomicAdd(&d_gsum[g * HIDN + c], asum);
            atomicMax(&d_gmaxk[g * HIDN + c], enc_f(amax));
            if (c == 0) atomicAdd(&d_gcnt[g], cnt);
            g = gn; asum = 0.f; amax = -3.402823466e38f; cnt = 0;
        }
        float val = h[(size_t)i * HIDN + c];
        asum += val;
        amax = fmaxf(amax, val);
        cnt++;
    }
    atomicAdd(&d_gsum[g * HIDN + c], asum);
    atomicMax(&d_gmaxk[g * HIDN + c], enc_f(amax));
    if (c == 0) atomicAdd(&d_gcnt[g], cnt);
}

// ---------------- graph head: relu([mean|max|sum] @ W1 + b1) @ W2 + b2 ----------------
__global__ void mlp_kernel(const float* __restrict__ W1, const float* __restrict__ b1,
                           const float* __restrict__ W2, const float* __restrict__ b2,
                           float* __restrict__ gout) {
    __shared__ float pooled[384];
    __shared__ float t[128];
    int g = blockIdx.x, c = threadIdx.x;
    float cnt = fmaxf((float)d_gcnt[g], 1.f);
    float sv = d_gsum[g * HIDN + c];
    pooled[c] = sv / cnt;
    pooled[128 + c] = dec_f(d_gmaxk[g * HIDN + c]);
    pooled[256 + c] = sv;
    __syncthreads();
    float acc = b1[c];
#pragma unroll 8
    for (int kk = 0; kk < 384; kk++) acc = fmaf(pooled[kk], W1[kk * 128 + c], acc);
    t[c] = fmaxf(acc, 0.f);
    __syncthreads();
    float o = b2[c];
#pragma unroll 8
    for (int kk = 0; kk < 128; kk++) o = fmaf(t[kk], W2[kk * 128 + c], o);
    gout[g * 128 + c] = o;
}

// ---------------- driver ----------------
extern "C" void kernel_launch(void* const* d_in, const int* in_sizes, int n_in,
                              void* d_out, int out_size) {
    const float* x     = (const float*)d_in[0];
    const int*   ei    = (const int*)d_in[1];
    const float* eattr = (const float*)d_in[2];
    const int*   batch = (const int*)d_in[3];
    const float* W_in  = (const float*)d_in[4];
    const float* b_in  = (const float*)d_in[5];
    const float* Wq    = (const float*)d_in[6];
    const float* bq    = (const float*)d_in[7];
    const float* Wk    = (const float*)d_in[8];
    const float* bk    = (const float*)d_in[9];
    const float* Wv    = (const float*)d_in[10];
    const float* bv    = (const float*)d_in[11];
    const float* We    = (const float*)d_in[12];
    const float* be    = (const float*)d_in[13];
    const float* Wo    = (const float*)d_in[14];
    const float* bo    = (const float*)d_in[15];
    const float* ln_g  = (const float*)d_in[16];
    const float* ln_b  = (const float*)d_in[17];
    const float* W_ep  = (const float*)d_in[18];
    const float* b_ep  = (const float*)d_in[19];
    const float* W1    = (const float*)d_in[20];
    const float* b1    = (const float*)d_in[21];
    const float* W2    = (const float*)d_in[22];
    const float* b2    = (const float*)d_in[23];

    int N = in_sizes[0] / 128;
    int E = in_sizes[1] / 2;

    float* out  = (float*)d_out;
    float* h    = out;                       // [N,128] lives directly in d_out
    float* gout = out + (size_t)N * HIDN;    // [G,128]

    void *pq, *pk, *pv, *ptmp, *pagg;
    cudaGetSymbolAddress(&pq, d_q);
    cudaGetSymbolAddress(&pk, d_k);
    cudaGetSymbolAddress(&pv, d_v);
    cudaGetSymbolAddress(&ptmp, d_tmp);
    cudaGetSymbolAddress(&pagg, d_agg);

    const int* src = ei;
    const int* dst = ei + E;

    int gE = (E + 255) / 256;
    int gN = (N + 255) / 256;
    int gW = (N + 7) / 8;         // warp-per-node kernels, 256-thread blocks
    int gEW = (E + 7) / 8;        // warp-per-edge
    int gGemm = (N + 127) / 128;

    // CSR build + edge projection (layer-independent)
    zero_csr_kernel<<<gN, 256>>>(N);
    hist_kernel<<<gE, 256>>>(dst, E);
    scan_kernel<<<1, 1024>>>(N);
    scatter_kernel<<<gE, 256>>>(src, dst, E);
    ea_proj_kernel<<<gEW, 256>>>(eattr, W_ep, b_ep, E);

    // input projection: h = x @ W_in + b_in
    gemm128_kernel<<<gGemm, 256>>>(x, W_in, b_in, h, N);

    for (int l = 0; l < 3; l++) {
        const float* Wq_l = Wq + (size_t)l * 128 * 128;
        const float* Wk_l = Wk + (size_t)l * 128 * 128;
        const float* Wv_l = Wv + (size_t)l * 128 * 128;
        const float* Wo_l = Wo + (size_t)l * 128 * 128;
        const float* We_l = We + (size_t)l * 32 * 128;

        gemm128_kernel<<<gGemm, 256>>>(h, Wq_l, bq + l * 128, (float*)pq, N);
        gemm128_kernel<<<gGemm, 256>>>(h, Wk_l, bk + l * 128, (float*)pk, N);
        gemm128_kernel<<<gGemm, 256>>>(h, Wv_l, bv + l * 128, (float*)pv, N);
        t_kernel<<<gW, 256>>>((const float*)pq, We_l, be + l * 128, N);
        edge_agg_kernel<<<gW, 256>>>(N);
        gemm128_kernel<<<gGemm, 256>>>((const float*)pagg, Wo_l, bo + l * 128, (float*)ptmp, N);
        ln_kernel<<<gW, 256>>>(h, ln_g + l * 128, ln_b + l * 128, N);
    }

    pool_init_kernel<<<(GG * HIDN + 255) / 256, 256>>>();
    pool_kernel<<<(N + NPB - 1) / NPB, 128>>>(h, batch, N);
    mlp_kernel<<<GG, 128>>>(W1, b1, W2, b2, gout);
}